// round 1
// baseline (speedup 1.0000x reference)
#include <cuda_runtime.h>
#include <math.h>

#define NN    3072
#define H     256
#define NB    4
#define HD    64
#define BH    1024   /* NB*H */

// ---------------- scratch (device globals; no runtime allocation) ----------
__device__ float  g_hn[NN * H];                       // 3 MB
__device__ float  g_k [NB * NN * HD];                 // 3 MB
__device__ float  g_mu[NB * NN * HD];                 // 3 MB
__device__ float  g_ls[NB * NN * HD];                 // 3 MB
__device__ float  g_a [(size_t)NB * NN * NN];         // 151 MB
__device__ float  g_att[(size_t)NN * BH];             // 12.6 MB
__device__ float  g_denom[NB * NN];
__device__ double g_kl;

// ---------------- init ------------------------------------------------------
__global__ void k_init() {
    int t = blockIdx.x * 256 + threadIdx.x;
    if (t < NB * NN) g_denom[t] = 0.0f;
    if (t == 0) g_kl = 0.0;
}

// ---------------- layernorm -------------------------------------------------
__global__ void k_ln(const float* __restrict__ h,
                     const float* __restrict__ gamma,
                     const float* __restrict__ beta) {
    int row = blockIdx.x;
    int tid = threadIdx.x;           // 256 threads, one per column
    float v = h[row * H + tid];

    __shared__ float red[8];
    float s = v;
    #pragma unroll
    for (int o = 16; o; o >>= 1) s += __shfl_xor_sync(0xffffffffu, s, o);
    if ((tid & 31) == 0) red[tid >> 5] = s;
    __syncthreads();
    float mean = 0.f;
    #pragma unroll
    for (int i = 0; i < 8; i++) mean += red[i];
    mean *= (1.0f / H);

    float d = v - mean;
    float q = d * d;
    #pragma unroll
    for (int o = 16; o; o >>= 1) q += __shfl_xor_sync(0xffffffffu, q, o);
    __syncthreads();
    if ((tid & 31) == 0) red[tid >> 5] = q;
    __syncthreads();
    float var = 0.f;
    #pragma unroll
    for (int i = 0; i < 8; i++) var += red[i];
    var *= (1.0f / H);

    g_hn[row * H + tid] = d * rsqrtf(var + 1e-5f) * gamma[tid] + beta[tid];
}

// ---------------- projections: K/MU/LS = hn @ W + b, head-major layout ------
// grid (48, 12): y = mat*4 + colchunk. Block tile 64x64, 256 thr, 4x4 micro.
__global__ void __launch_bounds__(256) k_proj(
    const float* __restrict__ Wk, const float* __restrict__ bk,
    const float* __restrict__ Wm, const float* __restrict__ bm,
    const float* __restrict__ Wl, const float* __restrict__ bl)
{
    __shared__ float As[64][68];
    __shared__ float Bs[64][64];

    int mat = blockIdx.y >> 2;
    const float* W    = (mat == 0) ? Wk : (mat == 1) ? Wm : Wl;
    const float* bias = (mat == 0) ? bk : (mat == 1) ? bm : bl;
    float*       out  = (mat == 0) ? g_k : (mat == 1) ? g_mu : g_ls;

    int m0 = blockIdx.x * 64;
    int j0 = (blockIdx.y & 3) * 64;
    int tid = threadIdx.x;
    int tx = tid & 15, ty = tid >> 4;

    float acc[4][4] = {};

    for (int kk = 0; kk < H; kk += 64) {
        for (int i = tid; i < 64 * 16; i += 256) {
            int r = i >> 4, c = (i & 15) << 2;
            *(float4*)&As[r][c] = *(const float4*)&g_hn[(size_t)(m0 + r) * H + kk + c];
            *(float4*)&Bs[r][c] = *(const float4*)&W[(size_t)(kk + r) * H + j0 + c];
        }
        __syncthreads();
        #pragma unroll 8
        for (int k = 0; k < 64; k++) {
            float a[4], b[4];
            #pragma unroll
            for (int i = 0; i < 4; i++) a[i] = As[ty + 16 * i][k];
            #pragma unroll
            for (int j = 0; j < 4; j++) b[j] = Bs[k][tx + 16 * j];
            #pragma unroll
            for (int i = 0; i < 4; i++)
                #pragma unroll
                for (int j = 0; j < 4; j++)
                    acc[i][j] = fmaf(a[i], b[j], acc[i][j]);
        }
        __syncthreads();
    }

    #pragma unroll
    for (int i = 0; i < 4; i++) {
        int m = m0 + ty + 16 * i;
        #pragma unroll
        for (int j = 0; j < 4; j++) {
            int jc = j0 + tx + 16 * j;
            float v = acc[i][j] + bias[jc];
            int b = jc & 3, d = jc >> 2;   // reshape(N, HD, B): col = d*B + b
            out[((size_t)b * NN + m) * HD + d] = v;
        }
    }
}

// ---------------- scores + softplus + KL + sample -> a ----------------------
// grid (4, 48, 48): x = head (adjacent heads co-scheduled -> eps L2 reuse)
// Block computes 64x64 tile of S_mu,S_ls for one head, then elementwise.
__global__ void __launch_bounds__(256) k_scores(const float* __restrict__ diffusion,
                                                const float* __restrict__ eps)
{
    extern __shared__ float sm[];
    float (*Ks)[68] = (float(*)[68])sm;
    float (*Ms)[68] = (float(*)[68])(sm + 64 * 68);
    float (*Ls)[68] = (float(*)[68])(sm + 2 * 64 * 68);

    int b  = blockIdx.x;
    int x0 = blockIdx.y * 64;
    int y0 = blockIdx.z * 64;

    const float* kp = g_k  + (size_t)b * NN * HD;
    const float* mp = g_mu + (size_t)b * NN * HD;
    const float* lp = g_ls + (size_t)b * NN * HD;

    int tid = threadIdx.x;
    int tx = tid & 15, ty = tid >> 4;

    for (int i = tid; i < 64 * 16; i += 256) {
        int r = i >> 4, c = (i & 15) << 2;
        *(float4*)&Ks[r][c] = *(const float4*)&kp[(size_t)(x0 + r) * HD + c];
        *(float4*)&Ms[r][c] = *(const float4*)&mp[(size_t)(y0 + r) * HD + c];
        *(float4*)&Ls[r][c] = *(const float4*)&lp[(size_t)(y0 + r) * HD + c];
    }
    __syncthreads();

    float accm[4][4] = {}, accl[4][4] = {};
    for (int k = 0; k < 64; k += 4) {
        float4 kf[4], mf[4], lf[4];
        #pragma unroll
        for (int i = 0; i < 4; i++) kf[i] = *(const float4*)&Ks[ty + 16 * i][k];
        #pragma unroll
        for (int j = 0; j < 4; j++) {
            mf[j] = *(const float4*)&Ms[tx + 16 * j][k];
            lf[j] = *(const float4*)&Ls[tx + 16 * j][k];
        }
        #pragma unroll
        for (int i = 0; i < 4; i++)
            #pragma unroll
            for (int j = 0; j < 4; j++) {
                accm[i][j] = fmaf(kf[i].x, mf[j].x, accm[i][j]);
                accm[i][j] = fmaf(kf[i].y, mf[j].y, accm[i][j]);
                accm[i][j] = fmaf(kf[i].z, mf[j].z, accm[i][j]);
                accm[i][j] = fmaf(kf[i].w, mf[j].w, accm[i][j]);
                accl[i][j] = fmaf(kf[i].x, lf[j].x, accl[i][j]);
                accl[i][j] = fmaf(kf[i].y, lf[j].y, accl[i][j]);
                accl[i][j] = fmaf(kf[i].z, lf[j].z, accl[i][j]);
                accl[i][j] = fmaf(kf[i].w, lf[j].w, accl[i][j]);
            }
    }

    // ---- elementwise epilogue ----
    float* ap = g_a + (size_t)b * NN * NN;
    float klsum = 0.f;
    float rsum[4] = {0.f, 0.f, 0.f, 0.f};

    #pragma unroll
    for (int i = 0; i < 4; i++) {
        int x = x0 + ty + 16 * i;
        #pragma unroll
        for (int j = 0; j < 4; j++) {
            int y = y0 + tx + 16 * j;
            size_t xy = (size_t)x * NN + y;
            float smu = accm[i][j] * 0.125f;           // HD^-0.5
            float sls = accl[i][j] * 0.125f;
            // stable softplus = max(x,0) + log1p(exp(-|x|))
            float sig = fmaxf(sls, 0.f) + log1pf(__expf(-fabsf(sls)));
            float dif = diffusion[xy];
            float ev  = eps[xy * NB + b];
            // KL(LogN(mu,sig) || LogN(0,1)) = -log(sig) + (sig^2+mu^2)/2 - 1/2
            float kle = 0.5f * (sig * sig + smu * smu) - __logf(sig) - 0.5f;
            float sgn = (dif > 0.f) ? 1.f : ((dif < 0.f) ? -1.f : 0.f);
            klsum += kle * sgn;
            float a = __expf(smu + sig * ev) * dif;
            ap[xy] = a;
            rsum[i] += fabsf(a);
        }
    }

    // per-row denom: reduce over tx (half-warp), then one atomic per row
    #pragma unroll
    for (int i = 0; i < 4; i++) {
        float r = rsum[i];
        #pragma unroll
        for (int o = 8; o; o >>= 1) r += __shfl_xor_sync(0xffffffffu, r, o);
        if (tx == 0) atomicAdd(&g_denom[b * NN + x0 + ty + 16 * i], r);
    }

    // kl: warp reduce -> smem -> one double atomic per block
    #pragma unroll
    for (int o = 16; o; o >>= 1) klsum += __shfl_xor_sync(0xffffffffu, klsum, o);
    __shared__ float kred[8];
    if ((tid & 31) == 0) kred[tid >> 5] = klsum;
    __syncthreads();
    if (tid == 0) {
        float s = 0.f;
        #pragma unroll
        for (int i = 0; i < 8; i++) s += kred[i];
        atomicAdd(&g_kl, (double)s);
    }
}

// ---------------- aggregation: out[x, b*H+h] = (1/denom) sum_y a[b,x,y] hn[y,h]
// grid (24, 8). Block tile 128x128, 256 thr, 8x8 micro, K-chunk 64 over y.
__global__ void __launch_bounds__(256) k_agg()
{
    extern __shared__ float sm[];
    float (*As)[68]  = (float(*)[68])sm;              // 128 x 64 (a tile)
    float (*Bs)[128] = (float(*)[128])(sm + 128 * 68); // 64 x 128 (hn tile)

    int x0    = blockIdx.x * 128;
    int gcol0 = blockIdx.y * 128;       // column in [0, BH)
    int b     = gcol0 >> 8;             // head
    int hbase = gcol0 & 255;            // offset within head (0 or 128)

    const float* ap = g_a + (size_t)b * NN * NN;
    int tid = threadIdx.x;
    int tx = tid & 15, ty = tid >> 4;

    float acc[8][8] = {};

    for (int kk = 0; kk < NN; kk += 64) {
        for (int i = tid; i < 128 * 16; i += 256) {
            int r = i >> 4, c = (i & 15) << 2;
            *(float4*)&As[r][c] = *(const float4*)&ap[(size_t)(x0 + r) * NN + kk + c];
        }
        for (int i = tid; i < 64 * 32; i += 256) {
            int r = i >> 5, c = (i & 31) << 2;
            *(float4*)&Bs[r][c] = *(const float4*)&g_hn[(size_t)(kk + r) * H + hbase + c];
        }
        __syncthreads();
        #pragma unroll 4
        for (int k = 0; k < 64; k++) {
            float av[8];
            #pragma unroll
            for (int i = 0; i < 8; i++) av[i] = As[ty * 8 + i][k];
            float4 b0 = *(const float4*)&Bs[k][tx * 4];
            float4 b1 = *(const float4*)&Bs[k][64 + tx * 4];
            #pragma unroll
            for (int i = 0; i < 8; i++) {
                acc[i][0] = fmaf(av[i], b0.x, acc[i][0]);
                acc[i][1] = fmaf(av[i], b0.y, acc[i][1]);
                acc[i][2] = fmaf(av[i], b0.z, acc[i][2]);
                acc[i][3] = fmaf(av[i], b0.w, acc[i][3]);
                acc[i][4] = fmaf(av[i], b1.x, acc[i][4]);
                acc[i][5] = fmaf(av[i], b1.y, acc[i][5]);
                acc[i][6] = fmaf(av[i], b1.z, acc[i][6]);
                acc[i][7] = fmaf(av[i], b1.w, acc[i][7]);
            }
        }
        __syncthreads();
    }

    #pragma unroll
    for (int i = 0; i < 8; i++) {
        int x = x0 + ty * 8 + i;
        float invd = 1.0f / fmaxf(g_denom[b * NN + x], 1e-12f);
        float4 v0, v1;
        v0.x = acc[i][0] * invd; v0.y = acc[i][1] * invd;
        v0.z = acc[i][2] * invd; v0.w = acc[i][3] * invd;
        v1.x = acc[i][4] * invd; v1.y = acc[i][5] * invd;
        v1.z = acc[i][6] * invd; v1.w = acc[i][7] * invd;
        *(float4*)&g_att[(size_t)x * BH + gcol0 + tx * 4]      = v0;
        *(float4*)&g_att[(size_t)x * BH + gcol0 + 64 + tx * 4] = v1;
    }
}

// ---------------- fc_v + elu + residual -------------------------------------
// out = elu(att @ W_v + b_v) + h0.  grid (24, 2), 128x128 tile, K=1024.
__global__ void __launch_bounds__(256) k_fc(const float* __restrict__ Wv,
                                            const float* __restrict__ bv,
                                            const float* __restrict__ h0,
                                            float* __restrict__ out)
{
    extern __shared__ float sm[];
    float (*As)[68]  = (float(*)[68])sm;               // 128 x 64 (att tile)
    float (*Bs)[128] = (float(*)[128])(sm + 128 * 68);  // 64 x 128 (W_v tile)

    int x0 = blockIdx.x * 128;
    int c0 = blockIdx.y * 128;
    int tid = threadIdx.x;
    int tx = tid & 15, ty = tid >> 4;

    float acc[8][8] = {};

    for (int kk = 0; kk < BH; kk += 64) {
        for (int i = tid; i < 128 * 16; i += 256) {
            int r = i >> 4, c = (i & 15) << 2;
            *(float4*)&As[r][c] = *(const float4*)&g_att[(size_t)(x0 + r) * BH + kk + c];
        }
        for (int i = tid; i < 64 * 32; i += 256) {
            int r = i >> 5, c = (i & 31) << 2;
            *(float4*)&Bs[r][c] = *(const float4*)&Wv[(size_t)(kk + r) * H + c0 + c];
        }
        __syncthreads();
        #pragma unroll 4
        for (int k = 0; k < 64; k++) {
            float av[8];
            #pragma unroll
            for (int i = 0; i < 8; i++) av[i] = As[ty * 8 + i][k];
            float4 b0 = *(const float4*)&Bs[k][tx * 4];
            float4 b1 = *(const float4*)&Bs[k][64 + tx * 4];
            #pragma unroll
            for (int i = 0; i < 8; i++) {
                acc[i][0] = fmaf(av[i], b0.x, acc[i][0]);
                acc[i][1] = fmaf(av[i], b0.y, acc[i][1]);
                acc[i][2] = fmaf(av[i], b0.z, acc[i][2]);
                acc[i][3] = fmaf(av[i], b0.w, acc[i][3]);
                acc[i][4] = fmaf(av[i], b1.x, acc[i][4]);
                acc[i][5] = fmaf(av[i], b1.y, acc[i][5]);
                acc[i][6] = fmaf(av[i], b1.z, acc[i][6]);
                acc[i][7] = fmaf(av[i], b1.w, acc[i][7]);
            }
        }
        __syncthreads();
    }

    #pragma unroll
    for (int i = 0; i < 8; i++) {
        int x = x0 + ty * 8 + i;
        #pragma unroll
        for (int half = 0; half < 2; half++) {
            float4 v;
            float* a = &acc[i][half * 4];
            int col = c0 + half * 64 + tx * 4;
            float r0 = a[0] + bv[col + 0];
            float r1 = a[1] + bv[col + 1];
            float r2 = a[2] + bv[col + 2];
            float r3 = a[3] + bv[col + 3];
            r0 = (r0 > 0.f) ? r0 : expm1f(r0);
            r1 = (r1 > 0.f) ? r1 : expm1f(r1);
            r2 = (r2 > 0.f) ? r2 : expm1f(r2);
            r3 = (r3 > 0.f) ? r3 : expm1f(r3);
            v.x = r0 + h0[(size_t)x * H + col + 0];
            v.y = r1 + h0[(size_t)x * H + col + 1];
            v.z = r2 + h0[(size_t)x * H + col + 2];
            v.w = r3 + h0[(size_t)x * H + col + 3];
            *(float4*)&out[(size_t)x * H + col] = v;
        }
    }
}

// ---------------- kl scalar output ------------------------------------------
__global__ void k_klout(float* __restrict__ out, int out_size) {
    if (threadIdx.x == 0 && out_size > NN * H) {
        out[out_size - 1] = (float)(g_kl / (double)((size_t)NN * NN));
    }
}

// ---------------- launch -----------------------------------------------------
extern "C" void kernel_launch(void* const* d_in, const int* in_sizes, int n_in,
                              void* d_out, int out_size)
{
    const float* h     = (const float*)d_in[0];
    const float* gamma = (const float*)d_in[1];
    const float* beta  = (const float*)d_in[2];
    const float* Wk    = (const float*)d_in[3];
    const float* bk    = (const float*)d_in[4];
    const float* Wm    = (const float*)d_in[5];
    const float* bm    = (const float*)d_in[6];
    const float* Wl    = (const float*)d_in[7];
    const float* bl    = (const float*)d_in[8];
    const float* Wv    = (const float*)d_in[9];
    const float* bv    = (const float*)d_in[10];
    const float* diff  = (const float*)d_in[11];
    const float* eps   = (const float*)d_in[12];
    float* out = (float*)d_out;

    const int smem_scores = 3 * 64 * 68 * 4;                 // 52224 B
    const int smem_gemm   = (128 * 68 + 64 * 128) * 4;       // 67584 B
    cudaFuncSetAttribute(k_scores, cudaFuncAttributeMaxDynamicSharedMemorySize, smem_scores);
    cudaFuncSetAttribute(k_agg,    cudaFuncAttributeMaxDynamicSharedMemorySize, smem_gemm);
    cudaFuncSetAttribute(k_fc,     cudaFuncAttributeMaxDynamicSharedMemorySize, smem_gemm);

    k_init<<<48, 256>>>();
    k_ln<<<NN, 256>>>(h, gamma, beta);
    k_proj<<<dim3(48, 12), 256>>>(Wk, bk, Wm, bm, Wl, bl);
    k_scores<<<dim3(NB, 48, 48), 256, smem_scores>>>(diff, eps);
    k_agg<<<dim3(24, 8), 256, smem_gemm>>>();
    k_fc<<<dim3(24, 2), 256, smem_gemm>>>(Wv, bv, h, out);
    k_klout<<<1, 32>>>(out, out_size);
}

// round 3
// speedup vs baseline: 1.4112x; 1.4112x over previous
#include <cuda_runtime.h>
#include <cuda_bf16.h>
#include <math.h>
#include <stdint.h>

#define NN    3072
#define H     256
#define NB    4
#define HD    64
#define BH    1024   /* NB*H */

// ---------------- scratch (device globals; no runtime allocation) ----------
__device__ float          g_hn[NN * H];                       // 3 MB
__device__ float          g_k [NB * NN * HD];                 // 3 MB
__device__ float          g_mu[NB * NN * HD];                 // 3 MB
__device__ float          g_ls[NB * NN * HD];                 // 3 MB
__device__ __nv_bfloat16  g_a_hi[(size_t)NB * NN * NN];       // 75.5 MB
__device__ __nv_bfloat16  g_a_lo[(size_t)NB * NN * NN];       // 75.5 MB
__device__ __nv_bfloat16  g_hnb_hi[(size_t)NN * H];           // 1.5 MB
__device__ __nv_bfloat16  g_hnb_lo[(size_t)NN * H];           // 1.5 MB
__device__ float          g_att[(size_t)NN * BH];             // 12.6 MB
__device__ float          g_denom[NB * NN];
__device__ double         g_kl;

// ---------------- PTX helpers ------------------------------------------------
__device__ __forceinline__ uint32_t smem_u32(const void* p) {
    uint32_t a;
    asm("{ .reg .u64 t; cvta.to.shared.u64 t, %1; cvt.u32.u64 %0, t; }"
        : "=r"(a) : "l"(p));
    return a;
}

__device__ __forceinline__ void cp16(uint32_t s, const void* g) {
    asm volatile("cp.async.cg.shared.global [%0], [%1], 16;" :: "r"(s), "l"(g));
}
#define CP_COMMIT() asm volatile("cp.async.commit_group;" ::: "memory")
#define CP_WAIT(n)  asm volatile("cp.async.wait_group %0;" :: "n"(n) : "memory")

#define LDSM_X4(r0, r1, r2, r3, addr) \
    asm volatile("ldmatrix.sync.aligned.m8n8.x4.shared.b16 {%0,%1,%2,%3}, [%4];" \
                 : "=r"(r0), "=r"(r1), "=r"(r2), "=r"(r3) : "r"(addr))

#define LDSM_X4_T(r0, r1, r2, r3, addr) \
    asm volatile("ldmatrix.sync.aligned.m8n8.x4.trans.shared.b16 {%0,%1,%2,%3}, [%4];" \
                 : "=r"(r0), "=r"(r1), "=r"(r2), "=r"(r3) : "r"(addr))

#define MMA_BF16(d, a, b0, b1) \
    asm volatile("mma.sync.aligned.m16n8k16.row.col.f32.bf16.bf16.f32 " \
                 "{%0,%1,%2,%3}, {%4,%5,%6,%7}, {%8,%9}, {%0,%1,%2,%3};" \
                 : "+f"((d)[0]), "+f"((d)[1]), "+f"((d)[2]), "+f"((d)[3]) \
                 : "r"((a)[0]), "r"((a)[1]), "r"((a)[2]), "r"((a)[3]), \
                   "r"(b0), "r"(b1))

// ---------------- init ------------------------------------------------------
__global__ void k_init() {
    int t = blockIdx.x * 256 + threadIdx.x;
    if (t < NB * NN) g_denom[t] = 0.0f;
    if (t == 0) g_kl = 0.0;
}

// ---------------- layernorm -------------------------------------------------
__global__ void k_ln(const float* __restrict__ h,
                     const float* __restrict__ gamma,
                     const float* __restrict__ beta) {
    int row = blockIdx.x;
    int tid = threadIdx.x;
    float v = h[row * H + tid];

    __shared__ float red[8];
    float s = v;
    #pragma unroll
    for (int o = 16; o; o >>= 1) s += __shfl_xor_sync(0xffffffffu, s, o);
    if ((tid & 31) == 0) red[tid >> 5] = s;
    __syncthreads();
    float mean = 0.f;
    #pragma unroll
    for (int i = 0; i < 8; i++) mean += red[i];
    mean *= (1.0f / H);

    float d = v - mean;
    float q = d * d;
    #pragma unroll
    for (int o = 16; o; o >>= 1) q += __shfl_xor_sync(0xffffffffu, q, o);
    __syncthreads();
    if ((tid & 31) == 0) red[tid >> 5] = q;
    __syncthreads();
    float var = 0.f;
    #pragma unroll
    for (int i = 0; i < 8; i++) var += red[i];
    var *= (1.0f / H);

    g_hn[row * H + tid] = d * rsqrtf(var + 1e-5f) * gamma[tid] + beta[tid];
}

// ---------------- hn -> bf16 hi/lo split (natural layout) --------------------
__global__ void k_hnb() {
    int i = blockIdx.x * 256 + threadIdx.x;
    float v = g_hn[i];
    __nv_bfloat16 hi = __float2bfloat16(v);
    g_hnb_hi[i] = hi;
    g_hnb_lo[i] = __float2bfloat16(v - __bfloat162float(hi));
}

// ---------------- projections -----------------------------------------------
__global__ void __launch_bounds__(256) k_proj(
    const float* __restrict__ Wk, const float* __restrict__ bk,
    const float* __restrict__ Wm, const float* __restrict__ bm,
    const float* __restrict__ Wl, const float* __restrict__ bl)
{
    __shared__ float As[64][68];
    __shared__ float Bs[64][64];

    int mat = blockIdx.y >> 2;
    const float* W    = (mat == 0) ? Wk : (mat == 1) ? Wm : Wl;
    const float* bias = (mat == 0) ? bk : (mat == 1) ? bm : bl;
    float*       out  = (mat == 0) ? g_k : (mat == 1) ? g_mu : g_ls;

    int m0 = blockIdx.x * 64;
    int j0 = (blockIdx.y & 3) * 64;
    int tid = threadIdx.x;
    int tx = tid & 15, ty = tid >> 4;

    float acc[4][4] = {};

    for (int kk = 0; kk < H; kk += 64) {
        for (int i = tid; i < 64 * 16; i += 256) {
            int r = i >> 4, c = (i & 15) << 2;
            *(float4*)&As[r][c] = *(const float4*)&g_hn[(size_t)(m0 + r) * H + kk + c];
            *(float4*)&Bs[r][c] = *(const float4*)&W[(size_t)(kk + r) * H + j0 + c];
        }
        __syncthreads();
        #pragma unroll 8
        for (int k = 0; k < 64; k++) {
            float a[4], b[4];
            #pragma unroll
            for (int i = 0; i < 4; i++) a[i] = As[ty + 16 * i][k];
            #pragma unroll
            for (int j = 0; j < 4; j++) b[j] = Bs[k][tx + 16 * j];
            #pragma unroll
            for (int i = 0; i < 4; i++)
                #pragma unroll
                for (int j = 0; j < 4; j++)
                    acc[i][j] = fmaf(a[i], b[j], acc[i][j]);
        }
        __syncthreads();
    }

    #pragma unroll
    for (int i = 0; i < 4; i++) {
        int m = m0 + ty + 16 * i;
        #pragma unroll
        for (int j = 0; j < 4; j++) {
            int jc = j0 + tx + 16 * j;
            float v = acc[i][j] + bias[jc];
            int b = jc & 3, d = jc >> 2;
            out[((size_t)b * NN + m) * HD + d] = v;
        }
    }
}

// ---------------- scores + softplus + KL + sample -> a_hi/a_lo ---------------
__global__ void __launch_bounds__(256) k_scores(const float* __restrict__ diffusion,
                                                const float* __restrict__ eps)
{
    extern __shared__ float sm[];
    float (*Ks)[68] = (float(*)[68])sm;
    float (*Ms)[68] = (float(*)[68])(sm + 64 * 68);
    float (*Ls)[68] = (float(*)[68])(sm + 2 * 64 * 68);

    int b  = blockIdx.x;
    int x0 = blockIdx.y * 64;
    int y0 = blockIdx.z * 64;

    const float* kp = g_k  + (size_t)b * NN * HD;
    const float* mp = g_mu + (size_t)b * NN * HD;
    const float* lp = g_ls + (size_t)b * NN * HD;

    int tid = threadIdx.x;
    int tx = tid & 15, ty = tid >> 4;

    for (int i = tid; i < 64 * 16; i += 256) {
        int r = i >> 4, c = (i & 15) << 2;
        *(float4*)&Ks[r][c] = *(const float4*)&kp[(size_t)(x0 + r) * HD + c];
        *(float4*)&Ms[r][c] = *(const float4*)&mp[(size_t)(y0 + r) * HD + c];
        *(float4*)&Ls[r][c] = *(const float4*)&lp[(size_t)(y0 + r) * HD + c];
    }
    __syncthreads();

    float accm[4][4] = {}, accl[4][4] = {};
    for (int k = 0; k < 64; k += 4) {
        float4 kf[4], mf[4], lf[4];
        #pragma unroll
        for (int i = 0; i < 4; i++) kf[i] = *(const float4*)&Ks[ty + 16 * i][k];
        #pragma unroll
        for (int j = 0; j < 4; j++) {
            mf[j] = *(const float4*)&Ms[tx + 16 * j][k];
            lf[j] = *(const float4*)&Ls[tx + 16 * j][k];
        }
        #pragma unroll
        for (int i = 0; i < 4; i++)
            #pragma unroll
            for (int j = 0; j < 4; j++) {
                accm[i][j] = fmaf(kf[i].x, mf[j].x, accm[i][j]);
                accm[i][j] = fmaf(kf[i].y, mf[j].y, accm[i][j]);
                accm[i][j] = fmaf(kf[i].z, mf[j].z, accm[i][j]);
                accm[i][j] = fmaf(kf[i].w, mf[j].w, accm[i][j]);
                accl[i][j] = fmaf(kf[i].x, lf[j].x, accl[i][j]);
                accl[i][j] = fmaf(kf[i].y, lf[j].y, accl[i][j]);
                accl[i][j] = fmaf(kf[i].z, lf[j].z, accl[i][j]);
                accl[i][j] = fmaf(kf[i].w, lf[j].w, accl[i][j]);
            }
    }

    __syncthreads();  // done reading Ks/Ms/Ls — reuse as bf16 staging

    __nv_bfloat16 (*Shi)[64] = (__nv_bfloat16(*)[64])sm;
    __nv_bfloat16 (*Slo)[64] = (__nv_bfloat16(*)[64])(sm + 2048);

    float klsum = 0.f;
    float rsum[4] = {0.f, 0.f, 0.f, 0.f};

    #pragma unroll
    for (int i = 0; i < 4; i++) {
        int x = x0 + ty + 16 * i;
        #pragma unroll
        for (int j = 0; j < 4; j++) {
            int y = y0 + tx + 16 * j;
            size_t xy = (size_t)x * NN + y;
            float smu = accm[i][j] * 0.125f;
            float sls = accl[i][j] * 0.125f;
            float sig = fmaxf(sls, 0.f) + log1pf(__expf(-fabsf(sls)));
            float dif = diffusion[xy];
            float ev  = eps[xy * NB + b];
            float kle = 0.5f * (sig * sig + smu * smu) - __logf(sig) - 0.5f;
            float sgn = (dif > 0.f) ? 1.f : ((dif < 0.f) ? -1.f : 0.f);
            klsum += kle * sgn;
            float a = __expf(smu + sig * ev) * dif;
            __nv_bfloat16 ah = __float2bfloat16(a);
            Shi[ty + 16 * i][tx + 16 * j] = ah;
            Slo[ty + 16 * i][tx + 16 * j] = __float2bfloat16(a - __bfloat162float(ah));
            rsum[i] += fabsf(a);
        }
    }

    #pragma unroll
    for (int i = 0; i < 4; i++) {
        float r = rsum[i];
        #pragma unroll
        for (int o = 8; o; o >>= 1) r += __shfl_xor_sync(0xffffffffu, r, o);
        if (tx == 0) atomicAdd(&g_denom[b * NN + x0 + ty + 16 * i], r);
    }

    #pragma unroll
    for (int o = 16; o; o >>= 1) klsum += __shfl_xor_sync(0xffffffffu, klsum, o);
    __shared__ float kred[8];
    if ((tid & 31) == 0) kred[tid >> 5] = klsum;
    __syncthreads();
    if (tid == 0) {
        float s = 0.f;
        #pragma unroll
        for (int i = 0; i < 8; i++) s += kred[i];
        atomicAdd(&g_kl, (double)s);
    }

    __nv_bfloat16* dhi = g_a_hi + (size_t)b * NN * NN;
    __nv_bfloat16* dlo = g_a_lo + (size_t)b * NN * NN;
    for (int t = tid; t < 512; t += 256) {
        int r = t >> 3, c = (t & 7) * 8;
        size_t go = (size_t)(x0 + r) * NN + y0 + c;
        *(float4*)&dhi[go] = *(float4*)&Shi[r][c];
        *(float4*)&dlo[go] = *(float4*)&Slo[r][c];
    }
}

// ---------------- aggregation: mma.sync split-bf16 GEMM ----------------------
// Per head: C[3072,256] = a[3072,3072] @ hn[3072,256].
// grid (24, 2, 4) = (Mtile 128, Ntile 128, head). 256 thr = 8 warps (4m x 2n),
// warp tile 32x64, BK=32, 3-stage cp.async pipeline.
// smem stage: Ah[128x32] pad-80B rows, Al same, Bh[32x128] pad-272B rows, Bl.
#define A_HALF   10240          /* 128*80 */
#define B_HALF   8704           /* 32*272 */
#define ST_A     0
#define ST_B     (2 * A_HALF)   /* 20480 */
#define STAGE_B  (2 * A_HALF + 2 * B_HALF)  /* 37888 */
#define NSTAGE   3
#define AGG_SMEM (NSTAGE * STAGE_B)

__global__ void __launch_bounds__(256, 1) k_agg_mma()
{
    extern __shared__ char smc[];
    uint32_t sbase = smem_u32(smc);

    int tid  = threadIdx.x;
    int lane = tid & 31, wid = tid >> 5;
    int x0 = blockIdx.x * 128;
    int n0 = blockIdx.y * 128;
    int b  = blockIdx.z;

    const __nv_bfloat16* Ahi = g_a_hi + (size_t)b * NN * NN;
    const __nv_bfloat16* Alo = g_a_lo + (size_t)b * NN * NN;

    int warp_m = (wid & 3) * 32;
    int warp_n = (wid >> 2) * 64;

    // loader mapping
    int lc  = tid & 3,  lr  = tid >> 2;   // A: chunk 0-3, row base 0-63
    int lcb = tid & 15, lkr = tid >> 4;   // B: chunk 0-15, krow base 0-15

    // ldmatrix address components
    int rowA   = warp_m + (lane & 15);
    int achunk = lane >> 4;                               // 0/1 -> +k8
    int kB     = (lane & 7) + 8 * ((lane >> 3) & 1);
    int noffB  = (warp_n + ((lane >> 4) & 1) * 8) * 2;

    float d[2][8][4] = {};

    // ---- pipeline ----
    #pragma unroll
    for (int pst = 0; pst < NSTAGE - 1; pst++) {
        int kk = pst * 32;
        uint32_t st = sbase + pst * STAGE_B;
        #pragma unroll
        for (int p = 0; p < 2; p++) {
            int r = lr + p * 64;
            cp16(st + ST_A + r * 80 + lc * 16,          Ahi + (size_t)(x0 + r) * NN + kk + lc * 8);
            cp16(st + ST_A + A_HALF + r * 80 + lc * 16, Alo + (size_t)(x0 + r) * NN + kk + lc * 8);
            int kr = lkr + p * 16;
            cp16(st + ST_B + kr * 272 + lcb * 16,          g_hnb_hi + (size_t)(kk + kr) * H + n0 + lcb * 8);
            cp16(st + ST_B + B_HALF + kr * 272 + lcb * 16, g_hnb_lo + (size_t)(kk + kr) * H + n0 + lcb * 8);
        }
        CP_COMMIT();
    }

    const int NT = NN / 32;   // 96 k-tiles
    for (int it = 0; it < NT; it++) {
        CP_WAIT(NSTAGE - 2);
        __syncthreads();

        // prefetch tile it + NSTAGE - 1 into the stage we just freed
        int pf = it + NSTAGE - 1;
        if (pf < NT) {
            int kk = pf * 32;
            uint32_t st = sbase + (pf % NSTAGE) * STAGE_B;
            #pragma unroll
            for (int p = 0; p < 2; p++) {
                int r = lr + p * 64;
                cp16(st + ST_A + r * 80 + lc * 16,          Ahi + (size_t)(x0 + r) * NN + kk + lc * 8);
                cp16(st + ST_A + A_HALF + r * 80 + lc * 16, Alo + (size_t)(x0 + r) * NN + kk + lc * 8);
                int kr = lkr + p * 16;
                cp16(st + ST_B + kr * 272 + lcb * 16,          g_hnb_hi + (size_t)(kk + kr) * H + n0 + lcb * 8);
                cp16(st + ST_B + B_HALF + kr * 272 + lcb * 16, g_hnb_lo + (size_t)(kk + kr) * H + n0 + lcb * 8);
            }
        }
        CP_COMMIT();

        uint32_t st = sbase + (it % NSTAGE) * STAGE_B;

        #pragma unroll
        for (int s = 0; s < 2; s++) {
            uint32_t ah[2][4], al[2][4];
            #pragma unroll
            for (int mi = 0; mi < 2; mi++) {
                uint32_t aaddr = st + ST_A + (rowA + mi * 16) * 80 + (2 * s + achunk) * 16;
                LDSM_X4(ah[mi][0], ah[mi][1], ah[mi][2], ah[mi][3], aaddr);
                LDSM_X4(al[mi][0], al[mi][1], al[mi][2], al[mi][3], aaddr + A_HALF);
            }
            uint32_t bh[4][4], bl[4][4];
            #pragma unroll
            for (int j = 0; j < 4; j++) {
                uint32_t baddr = st + ST_B + (s * 16 + kB) * 272 + noffB + j * 32;
                LDSM_X4_T(bh[j][0], bh[j][1], bh[j][2], bh[j][3], baddr);
                LDSM_X4_T(bl[j][0], bl[j][1], bl[j][2], bl[j][3], baddr + B_HALF);
            }
            #pragma unroll
            for (int mi = 0; mi < 2; mi++)
                #pragma unroll
                for (int j8 = 0; j8 < 8; j8++) {
                    int bi = j8 >> 1, br = (j8 & 1) * 2;
                    MMA_BF16(d[mi][j8], ah[mi], bh[bi][br], bh[bi][br + 1]);
                    MMA_BF16(d[mi][j8], al[mi], bh[bi][br], bh[bi][br + 1]);
                    MMA_BF16(d[mi][j8], ah[mi], bl[bi][br], bl[bi][br + 1]);
                }
        }
    }

    // ---- epilogue ----
    #pragma unroll
    for (int mi = 0; mi < 2; mi++) {
        int row0 = x0 + warp_m + mi * 16 + (lane >> 2);
        float invd0 = 1.0f / fmaxf(g_denom[b * NN + row0],     1e-12f);
        float invd1 = 1.0f / fmaxf(g_denom[b * NN + row0 + 8], 1e-12f);
        #pragma unroll
        for (int j8 = 0; j8 < 8; j8++) {
            int col = b * 256 + n0 + warp_n + j8 * 8 + 2 * (lane & 3);
            float2 v0 = make_float2(d[mi][j8][0] * invd0, d[mi][j8][1] * invd0);
            float2 v1 = make_float2(d[mi][j8][2] * invd1, d[mi][j8][3] * invd1);
            *(float2*)&g_att[(size_t)row0 * BH + col]       = v0;
            *(float2*)&g_att[(size_t)(row0 + 8) * BH + col] = v1;
        }
    }
}

// ---------------- fc_v + elu + residual -------------------------------------
__global__ void __launch_bounds__(256) k_fc(const float* __restrict__ Wv,
                                            const float* __restrict__ bv,
                                            const float* __restrict__ h0,
                                            float* __restrict__ out)
{
    extern __shared__ float sm[];
    float (*As)[68]  = (float(*)[68])sm;
    float (*Bs)[128] = (float(*)[128])(sm + 128 * 68);

    int x0 = blockIdx.x * 128;
    int c0 = blockIdx.y * 128;
    int tid = threadIdx.x;
    int tx = tid & 15, ty = tid >> 4;

    float acc[8][8] = {};

    for (int kk = 0; kk < BH; kk += 64) {
        for (int i = tid; i < 128 * 16; i += 256) {
            int r = i >> 4, c = (i & 15) << 2;
            *(float4*)&As[r][c] = *(const float4*)&g_att[(size_t)(x0 + r) * BH + kk + c];
        }
        for (int i = tid; i < 64 * 32; i += 256) {
            int r = i >> 5, c = (i & 31) << 2;
            *(float4*)&Bs[r][c] = *(const float4*)&Wv[(size_t)(kk + r) * H + c0 + c];
        }
        __syncthreads();
        #pragma unroll 4
        for (int k = 0; k < 64; k++) {
            float av[8];
            #pragma unroll
            for (int i = 0; i < 8; i++) av[i] = As[ty * 8 + i][k];
            float4 b0 = *(const float4*)&Bs[k][tx * 4];
            float4 b1 = *(const float4*)&Bs[k][64 + tx * 4];
            #pragma unroll
            for (int i = 0; i < 8; i++) {
                acc[i][0] = fmaf(av[i], b0.x, acc[i][0]);
                acc[i][1] = fmaf(av[i], b0.y, acc[i][1]);
                acc[i][2] = fmaf(av[i], b0.z, acc[i][2]);
                acc[i][3] = fmaf(av[i], b0.w, acc[i][3]);
                acc[i][4] = fmaf(av[i], b1.x, acc[i][4]);
                acc[i][5] = fmaf(av[i], b1.y, acc[i][5]);
                acc[i][6] = fmaf(av[i], b1.z, acc[i][6]);
                acc[i][7] = fmaf(av[i], b1.w, acc[i][7]);
            }
        }
        __syncthreads();
    }

    #pragma unroll
    for (int i = 0; i < 8; i++) {
        int x = x0 + ty * 8 + i;
        #pragma unroll
        for (int half = 0; half < 2; half++) {
            float4 v;
            float* a = &acc[i][half * 4];
            int col = c0 + half * 64 + tx * 4;
            float r0 = a[0] + bv[col + 0];
            float r1 = a[1] + bv[col + 1];
            float r2 = a[2] + bv[col + 2];
            float r3 = a[3] + bv[col + 3];
            r0 = (r0 > 0.f) ? r0 : expm1f(r0);
            r1 = (r1 > 0.f) ? r1 : expm1f(r1);
            r2 = (r2 > 0.f) ? r2 : expm1f(r2);
            r3 = (r3 > 0.f) ? r3 : expm1f(r3);
            v.x = r0 + h0[(size_t)x * H + col + 0];
            v.y = r1 + h0[(size_t)x * H + col + 1];
            v.z = r2 + h0[(size_t)x * H + col + 2];
            v.w = r3 + h0[(size_t)x * H + col + 3];
            *(float4*)&out[(size_t)x * H + col] = v;
        }
    }
}

// ---------------- kl scalar output ------------------------------------------
__global__ void k_klout(float* __restrict__ out, int out_size) {
    if (threadIdx.x == 0 && out_size > NN * H) {
        out[out_size - 1] = (float)(g_kl / (double)((size_t)NN * NN));
    }
}

// ---------------- launch -----------------------------------------------------
extern "C" void kernel_launch(void* const* d_in, const int* in_sizes, int n_in,
                              void* d_out, int out_size)
{
    const float* h     = (const float*)d_in[0];
    const float* gamma = (const float*)d_in[1];
    const float* beta  = (const float*)d_in[2];
    const float* Wk    = (const float*)d_in[3];
    const float* bk    = (const float*)d_in[4];
    const float* Wm    = (const float*)d_in[5];
    const float* bm    = (const float*)d_in[6];
    const float* Wl    = (const float*)d_in[7];
    const float* bl    = (const float*)d_in[8];
    const float* Wv    = (const float*)d_in[9];
    const float* bv    = (const float*)d_in[10];
    const float* diff  = (const float*)d_in[11];
    const float* eps   = (const float*)d_in[12];
    float* out = (float*)d_out;

    const int smem_scores = 3 * 64 * 68 * 4;                 // 52224 B
    const int smem_gemm   = (128 * 68 + 64 * 128) * 4;       // 67584 B
    cudaFuncSetAttribute(k_scores,  cudaFuncAttributeMaxDynamicSharedMemorySize, smem_scores);
    cudaFuncSetAttribute(k_agg_mma, cudaFuncAttributeMaxDynamicSharedMemorySize, AGG_SMEM);
    cudaFuncSetAttribute(k_fc,      cudaFuncAttributeMaxDynamicSharedMemorySize, smem_gemm);

    k_init<<<48, 256>>>();
    k_ln<<<NN, 256>>>(h, gamma, beta);
    k_hnb<<<NN, 256>>>();
    k_proj<<<dim3(48, 12), 256>>>(Wk, bk, Wm, bm, Wl, bl);
    k_scores<<<dim3(NB, 48, 48), 256, smem_scores>>>(diff, eps);
    k_agg_mma<<<dim3(24, 2, NB), 256, AGG_SMEM>>>();
    k_fc<<<dim3(24, 2), 256, smem_gemm>>>(Wv, bv, h, out);
    k_klout<<<1, 32>>>(out, out_size);
}

// round 4
// speedup vs baseline: 1.7951x; 1.2720x over previous
#include <cuda_runtime.h>
#include <cuda_bf16.h>
#include <math.h>
#include <stdint.h>

#define NN    3072
#define H     256
#define NB    4
#define HD    64
#define BH    1024   /* NB*H */

// ---------------- scratch (device globals) ----------------------------------
__device__ float          g_hn[NN * H];                       // 3 MB
__device__ __nv_bfloat16  g_kb_hi [NB * NN * HD];
__device__ __nv_bfloat16  g_kb_lo [NB * NN * HD];
__device__ __nv_bfloat16  g_mub_hi[NB * NN * HD];
__device__ __nv_bfloat16  g_mub_lo[NB * NN * HD];
__device__ __nv_bfloat16  g_lsb_hi[NB * NN * HD];
__device__ __nv_bfloat16  g_lsb_lo[NB * NN * HD];
__device__ __nv_bfloat16  g_a_hi[(size_t)NB * NN * NN];       // 75.5 MB
__device__ __nv_bfloat16  g_a_lo[(size_t)NB * NN * NN];       // 75.5 MB
__device__ __nv_bfloat16  g_hnb_hi[(size_t)NN * H];
__device__ __nv_bfloat16  g_hnb_lo[(size_t)NN * H];
__device__ float          g_att[(size_t)NN * BH];             // 12.6 MB
__device__ float          g_denom[NB * NN];
__device__ double         g_kl;

// ---------------- PTX helpers ------------------------------------------------
__device__ __forceinline__ uint32_t smem_u32(const void* p) {
    uint32_t a;
    asm("{ .reg .u64 t; cvta.to.shared.u64 t, %1; cvt.u32.u64 %0, t; }"
        : "=r"(a) : "l"(p));
    return a;
}
__device__ __forceinline__ void cp16(uint32_t s, const void* g) {
    asm volatile("cp.async.cg.shared.global [%0], [%1], 16;" :: "r"(s), "l"(g));
}
#define CP_COMMIT() asm volatile("cp.async.commit_group;" ::: "memory")
#define CP_WAIT(n)  asm volatile("cp.async.wait_group %0;" :: "n"(n) : "memory")

#define LDSM_X4(r0, r1, r2, r3, addr) \
    asm volatile("ldmatrix.sync.aligned.m8n8.x4.shared.b16 {%0,%1,%2,%3}, [%4];" \
                 : "=r"(r0), "=r"(r1), "=r"(r2), "=r"(r3) : "r"(addr))

#define LDSM_X4_T(r0, r1, r2, r3, addr) \
    asm volatile("ldmatrix.sync.aligned.m8n8.x4.trans.shared.b16 {%0,%1,%2,%3}, [%4];" \
                 : "=r"(r0), "=r"(r1), "=r"(r2), "=r"(r3) : "r"(addr))

#define MMA_BF16(d, a, b0, b1) \
    asm volatile("mma.sync.aligned.m16n8k16.row.col.f32.bf16.bf16.f32 " \
                 "{%0,%1,%2,%3}, {%4,%5,%6,%7}, {%8,%9}, {%0,%1,%2,%3};" \
                 : "+f"((d)[0]), "+f"((d)[1]), "+f"((d)[2]), "+f"((d)[3]) \
                 : "r"((a)[0]), "r"((a)[1]), "r"((a)[2]), "r"((a)[3]), \
                   "r"(b0), "r"(b1))

// ---------------- init ------------------------------------------------------
__global__ void k_init() {
    int t = blockIdx.x * 256 + threadIdx.x;
    if (t < NB * NN) g_denom[t] = 0.0f;
    if (t == 0) g_kl = 0.0;
}

// ---------------- layernorm -------------------------------------------------
__global__ void k_ln(const float* __restrict__ h,
                     const float* __restrict__ gamma,
                     const float* __restrict__ beta) {
    int row = blockIdx.x;
    int tid = threadIdx.x;
    float v = h[row * H + tid];

    __shared__ float red[8];
    float s = v;
    #pragma unroll
    for (int o = 16; o; o >>= 1) s += __shfl_xor_sync(0xffffffffu, s, o);
    if ((tid & 31) == 0) red[tid >> 5] = s;
    __syncthreads();
    float mean = 0.f;
    #pragma unroll
    for (int i = 0; i < 8; i++) mean += red[i];
    mean *= (1.0f / H);

    float d = v - mean;
    float q = d * d;
    #pragma unroll
    for (int o = 16; o; o >>= 1) q += __shfl_xor_sync(0xffffffffu, q, o);
    __syncthreads();
    if ((tid & 31) == 0) red[tid >> 5] = q;
    __syncthreads();
    float var = 0.f;
    #pragma unroll
    for (int i = 0; i < 8; i++) var += red[i];
    var *= (1.0f / H);

    g_hn[row * H + tid] = d * rsqrtf(var + 1e-5f) * gamma[tid] + beta[tid];
}

// ---------------- hn -> bf16 hi/lo split --------------------------------------
__global__ void k_hnb() {
    int i = blockIdx.x * 256 + threadIdx.x;
    float v = g_hn[i];
    __nv_bfloat16 hi = __float2bfloat16(v);
    g_hnb_hi[i] = hi;
    g_hnb_lo[i] = __float2bfloat16(v - __bfloat162float(hi));
}

// ---------------- projections (fp32 SIMT, bf16 hi/lo epilogue) ----------------
__global__ void __launch_bounds__(256) k_proj(
    const float* __restrict__ Wk, const float* __restrict__ bk,
    const float* __restrict__ Wm, const float* __restrict__ bm,
    const float* __restrict__ Wl, const float* __restrict__ bl)
{
    __shared__ float As[64][68];
    __shared__ float Bs[64][64];

    int mat = blockIdx.y >> 2;
    const float* W    = (mat == 0) ? Wk : (mat == 1) ? Wm : Wl;
    const float* bias = (mat == 0) ? bk : (mat == 1) ? bm : bl;
    __nv_bfloat16* out_hi = (mat == 0) ? g_kb_hi : (mat == 1) ? g_mub_hi : g_lsb_hi;
    __nv_bfloat16* out_lo = (mat == 0) ? g_kb_lo : (mat == 1) ? g_mub_lo : g_lsb_lo;
    float scl = (mat == 0) ? 0.125f : 1.0f;   // fold HD^-0.5 into k

    int m0 = blockIdx.x * 64;
    int j0 = (blockIdx.y & 3) * 64;
    int tid = threadIdx.x;
    int tx = tid & 15, ty = tid >> 4;

    float acc[4][4] = {};

    for (int kk = 0; kk < H; kk += 64) {
        for (int i = tid; i < 64 * 16; i += 256) {
            int r = i >> 4, c = (i & 15) << 2;
            *(float4*)&As[r][c] = *(const float4*)&g_hn[(size_t)(m0 + r) * H + kk + c];
            *(float4*)&Bs[r][c] = *(const float4*)&W[(size_t)(kk + r) * H + j0 + c];
        }
        __syncthreads();
        #pragma unroll 8
        for (int k = 0; k < 64; k++) {
            float a[4], b[4];
            #pragma unroll
            for (int i = 0; i < 4; i++) a[i] = As[ty + 16 * i][k];
            #pragma unroll
            for (int j = 0; j < 4; j++) b[j] = Bs[k][tx + 16 * j];
            #pragma unroll
            for (int i = 0; i < 4; i++)
                #pragma unroll
                for (int j = 0; j < 4; j++)
                    acc[i][j] = fmaf(a[i], b[j], acc[i][j]);
        }
        __syncthreads();
    }

    #pragma unroll
    for (int i = 0; i < 4; i++) {
        int m = m0 + ty + 16 * i;
        #pragma unroll
        for (int j = 0; j < 4; j++) {
            int jc = j0 + tx + 16 * j;
            float v = (acc[i][j] + bias[jc]) * scl;
            int b = jc & 3, d = jc >> 2;   // reshape(N, HD, B)
            size_t o = ((size_t)b * NN + m) * HD + d;
            __nv_bfloat16 hi = __float2bfloat16(v);
            out_hi[o] = hi;
            out_lo[o] = __float2bfloat16(v - __bfloat162float(hi));
        }
    }
}

// ---------------- scores via tensor cores + elementwise -> a_hi/a_lo ----------
// grid (NB, 48, 48): 64x64 tile per CTA, 128 thr = 4 warps (2m x 2n, warp 32x32)
// smem: K hi/lo, MU hi/lo, LS hi/lo — 64 rows x 144B (pad) each = 6*9216 = 55296
#define SC_ROW 144
#define SC_HALF (64 * SC_ROW)     /* 9216 */
#define SC_SMEM (6 * SC_HALF)

__global__ void __launch_bounds__(128) k_scores_mma(const float* __restrict__ diffusion,
                                                    const float* __restrict__ eps)
{
    extern __shared__ char smc[];
    uint32_t sb = smem_u32(smc);

    int b  = blockIdx.x;
    int x0 = blockIdx.y * 64;
    int y0 = blockIdx.z * 64;
    int tid = threadIdx.x, lane = tid & 31, wid = tid >> 5;
    int warp_m = (wid & 1) * 32, warp_n = (wid >> 1) * 32;

    const __nv_bfloat16* Kh = g_kb_hi  + ((size_t)b * NN + x0) * HD;
    const __nv_bfloat16* Kl = g_kb_lo  + ((size_t)b * NN + x0) * HD;
    const __nv_bfloat16* Mh = g_mub_hi + ((size_t)b * NN + y0) * HD;
    const __nv_bfloat16* Ml = g_mub_lo + ((size_t)b * NN + y0) * HD;
    const __nv_bfloat16* Lh = g_lsb_hi + ((size_t)b * NN + y0) * HD;
    const __nv_bfloat16* Ll = g_lsb_lo + ((size_t)b * NN + y0) * HD;

    // load tiles (64 rows x 128B each half)
    {
        int lc = tid & 7, lr = tid >> 3;      // chunk 0-7, row 0-15
        #pragma unroll
        for (int p = 0; p < 4; p++) {
            int r = lr + p * 16;
            uint32_t so = r * SC_ROW + lc * 16;
            size_t  go = (size_t)r * HD + lc * 8;
            cp16(sb + 0 * SC_HALF + so, Kh + go);
            cp16(sb + 1 * SC_HALF + so, Kl + go);
            cp16(sb + 2 * SC_HALF + so, Mh + go);
            cp16(sb + 3 * SC_HALF + so, Ml + go);
            cp16(sb + 4 * SC_HALF + so, Lh + go);
            cp16(sb + 5 * SC_HALF + so, Ll + go);
        }
    }
    CP_COMMIT(); CP_WAIT(0);
    __syncthreads();

    float accm[2][4][4] = {}, accl[2][4][4] = {};
    int rA  = warp_m + (lane & 15);
    int cA8 = lane >> 4;
    int rB  = warp_n + (lane & 7) + 8 * ((lane >> 3) & 1);
    int cB8 = lane >> 4;

    #pragma unroll
    for (int s = 0; s < 4; s++) {
        uint32_t kh[2][4], kl[2][4];
        #pragma unroll
        for (int mi = 0; mi < 2; mi++) {
            uint32_t a = sb + (rA + mi * 16) * SC_ROW + s * 32 + cA8 * 16;
            LDSM_X4(kh[mi][0], kh[mi][1], kh[mi][2], kh[mi][3], a);
            LDSM_X4(kl[mi][0], kl[mi][1], kl[mi][2], kl[mi][3], a + SC_HALF);
        }
        uint32_t mh[2][4], ml[2][4], lh[2][4], ll[2][4];
        #pragma unroll
        for (int g = 0; g < 2; g++) {
            uint32_t bm = sb + 2 * SC_HALF + (rB + g * 16) * SC_ROW + s * 32 + cB8 * 16;
            LDSM_X4(mh[g][0], mh[g][1], mh[g][2], mh[g][3], bm);
            LDSM_X4(ml[g][0], ml[g][1], ml[g][2], ml[g][3], bm + SC_HALF);
            uint32_t bls = bm + 2 * SC_HALF;
            LDSM_X4(lh[g][0], lh[g][1], lh[g][2], lh[g][3], bls);
            LDSM_X4(ll[g][0], ll[g][1], ll[g][2], ll[g][3], bls + SC_HALF);
        }
        #pragma unroll
        for (int mi = 0; mi < 2; mi++)
            #pragma unroll
            for (int g = 0; g < 2; g++)
                #pragma unroll
                for (int nn = 0; nn < 2; nn++) {
                    int n8 = g * 2 + nn;
                    MMA_BF16(accm[mi][n8], kh[mi], mh[g][nn], mh[g][nn + 2]);
                    MMA_BF16(accm[mi][n8], kl[mi], mh[g][nn], mh[g][nn + 2]);
                    MMA_BF16(accm[mi][n8], kh[mi], ml[g][nn], ml[g][nn + 2]);
                    MMA_BF16(accl[mi][n8], kh[mi], lh[g][nn], lh[g][nn + 2]);
                    MMA_BF16(accl[mi][n8], kl[mi], lh[g][nn], lh[g][nn + 2]);
                    MMA_BF16(accl[mi][n8], kh[mi], ll[g][nn], ll[g][nn + 2]);
                }
    }

    __syncthreads();   // tiles dead — reuse [0, 2*SC_HALF) as bf16 staging

    float klsum = 0.f;
    float rsum[2][2] = {{0.f, 0.f}, {0.f, 0.f}};

    #pragma unroll
    for (int mi = 0; mi < 2; mi++) {
        int xl0 = warp_m + mi * 16 + (lane >> 2);
        #pragma unroll
        for (int n8 = 0; n8 < 4; n8++) {
            int yl = warp_n + n8 * 8 + 2 * (lane & 3);
            #pragma unroll
            for (int hf = 0; hf < 2; hf++) {
                int xl = xl0 + hf * 8;
                size_t xy = (size_t)(x0 + xl) * NN + (y0 + yl);
                float2 dif = *(const float2*)&diffusion[xy];
                float e0 = eps[xy * NB + b];
                float e1 = eps[(xy + 1) * NB + b];
                float smu0 = accm[mi][n8][hf * 2],     sls0 = accl[mi][n8][hf * 2];
                float smu1 = accm[mi][n8][hf * 2 + 1], sls1 = accl[mi][n8][hf * 2 + 1];
                float sig0 = fmaxf(sls0, 0.f) + log1pf(__expf(-fabsf(sls0)));
                float sig1 = fmaxf(sls1, 0.f) + log1pf(__expf(-fabsf(sls1)));
                float kle0 = 0.5f * (sig0 * sig0 + smu0 * smu0) - __logf(sig0) - 0.5f;
                float kle1 = 0.5f * (sig1 * sig1 + smu1 * smu1) - __logf(sig1) - 0.5f;
                float sg0 = (dif.x > 0.f) ? 1.f : ((dif.x < 0.f) ? -1.f : 0.f);
                float sg1 = (dif.y > 0.f) ? 1.f : ((dif.y < 0.f) ? -1.f : 0.f);
                klsum += kle0 * sg0 + kle1 * sg1;
                float a0 = __expf(smu0 + sig0 * e0) * dif.x;
                float a1 = __expf(smu1 + sig1 * e1) * dif.y;
                rsum[mi][hf] += fabsf(a0) + fabsf(a1);
                __nv_bfloat162 hi2, lo2;
                hi2.x = __float2bfloat16(a0);
                hi2.y = __float2bfloat16(a1);
                lo2.x = __float2bfloat16(a0 - __bfloat162float(hi2.x));
                lo2.y = __float2bfloat16(a1 - __bfloat162float(hi2.y));
                *(__nv_bfloat162*)(smc + xl * SC_ROW + yl * 2)           = hi2;
                *(__nv_bfloat162*)(smc + SC_HALF + xl * SC_ROW + yl * 2) = lo2;
            }
        }
    }

    // per-row denominators
    #pragma unroll
    for (int mi = 0; mi < 2; mi++)
        #pragma unroll
        for (int hf = 0; hf < 2; hf++) {
            float r = rsum[mi][hf];
            r += __shfl_xor_sync(0xffffffffu, r, 1);
            r += __shfl_xor_sync(0xffffffffu, r, 2);
            if ((lane & 3) == 0)
                atomicAdd(&g_denom[b * NN + x0 + warp_m + mi * 16 + hf * 8 + (lane >> 2)], r);
        }

    // KL
    #pragma unroll
    for (int o = 16; o; o >>= 1) klsum += __shfl_xor_sync(0xffffffffu, klsum, o);
    __shared__ float kred[4];
    if (lane == 0) kred[wid] = klsum;
    __syncthreads();
    if (tid == 0) {
        atomicAdd(&g_kl, (double)(kred[0] + kred[1] + kred[2] + kred[3]));
    }

    // coalesced copy-out
    __nv_bfloat16* dhi = g_a_hi + (size_t)b * NN * NN;
    __nv_bfloat16* dlo = g_a_lo + (size_t)b * NN * NN;
    for (int t = tid; t < 512; t += 128) {
        int r = t >> 3, c = t & 7;
        size_t go = (size_t)(x0 + r) * NN + y0 + c * 8;
        *(float4*)&dhi[go] = *(float4*)(smc + r * SC_ROW + c * 16);
        *(float4*)&dlo[go] = *(float4*)(smc + SC_HALF + r * SC_ROW + c * 16);
    }
}

// ---------------- aggregation: split-bf16 mma, CTA 128x256, warp 64x64 --------
#define A_HALF   10240                      /* 128*80 */
#define B_HALF   16896                      /* 32*528 */
#define ST_B_OFF (2 * A_HALF)               /* 20480 */
#define STAGE_BYTES (2 * A_HALF + 2 * B_HALF)   /* 54272 */
#define NSTAGE   3
#define AGG_SMEM (NSTAGE * STAGE_BYTES)     /* 162816 */

__device__ __forceinline__ void agg_load_stage(
    uint32_t st, int kk, int x0,
    const __nv_bfloat16* Ahi, const __nv_bfloat16* Alo,
    int lc, int lr, int lcb, int lkr)
{
    #pragma unroll
    for (int p = 0; p < 2; p++) {
        int r = lr + p * 64;
        uint32_t so = r * 80 + lc * 16;
        size_t  go = (size_t)(x0 + r) * NN + kk + lc * 8;
        cp16(st + so,          Ahi + go);
        cp16(st + A_HALF + so, Alo + go);
    }
    #pragma unroll
    for (int p = 0; p < 4; p++) {
        int kr = lkr + p * 8;
        uint32_t so = kr * 528 + lcb * 16;
        size_t  go = (size_t)(kk + kr) * H + lcb * 8;
        cp16(st + ST_B_OFF + so,          g_hnb_hi + go);
        cp16(st + ST_B_OFF + B_HALF + so, g_hnb_lo + go);
    }
}

__global__ void __launch_bounds__(256, 1) k_agg_mma()
{
    extern __shared__ char smc[];
    uint32_t sbase = smem_u32(smc);

    int tid  = threadIdx.x;
    int lane = tid & 31, wid = tid >> 5;
    int x0 = blockIdx.x * 128;
    int b  = blockIdx.y;

    const __nv_bfloat16* Ahi = g_a_hi + (size_t)b * NN * NN;
    const __nv_bfloat16* Alo = g_a_lo + (size_t)b * NN * NN;

    int warp_m = (wid & 1) * 64;
    int warp_n = (wid >> 1) * 64;

    int lc  = tid & 3,  lr  = tid >> 2;    // A loader
    int lcb = tid & 31, lkr = tid >> 5;    // B loader

    int rowA  = warp_m + (lane & 15);
    int achnk = lane >> 4;
    int kB    = (lane & 7) + 8 * ((lane >> 3) & 1);
    int noffB = (warp_n + ((lane >> 4) & 1) * 8) * 2;

    float d[4][8][4] = {};

    #pragma unroll
    for (int pst = 0; pst < NSTAGE - 1; pst++) {
        agg_load_stage(sbase + pst * STAGE_BYTES, pst * 32, x0, Ahi, Alo, lc, lr, lcb, lkr);
        CP_COMMIT();
    }

    const int NT = NN / 32;   // 96
    for (int it = 0; it < NT; it++) {
        CP_WAIT(NSTAGE - 2);
        __syncthreads();

        int pf = it + NSTAGE - 1;
        if (pf < NT)
            agg_load_stage(sbase + (pf % NSTAGE) * STAGE_BYTES, pf * 32, x0, Ahi, Alo, lc, lr, lcb, lkr);
        CP_COMMIT();

        uint32_t st = sbase + (it % NSTAGE) * STAGE_BYTES;

        #pragma unroll
        for (int s = 0; s < 2; s++) {
            uint32_t ah[4][4], al[4][4];
            #pragma unroll
            for (int mi = 0; mi < 4; mi++) {
                uint32_t aaddr = st + (rowA + mi * 16) * 80 + (s * 2 + achnk) * 16;
                LDSM_X4(ah[mi][0], ah[mi][1], ah[mi][2], ah[mi][3], aaddr);
                LDSM_X4(al[mi][0], al[mi][1], al[mi][2], al[mi][3], aaddr + A_HALF);
            }
            #pragma unroll
            for (int j = 0; j < 4; j++) {
                uint32_t bh[4], bl[4];
                uint32_t baddr = st + ST_B_OFF + (s * 16 + kB) * 528 + noffB + j * 32;
                LDSM_X4_T(bh[0], bh[1], bh[2], bh[3], baddr);
                LDSM_X4_T(bl[0], bl[1], bl[2], bl[3], baddr + B_HALF);
                #pragma unroll
                for (int mi = 0; mi < 4; mi++)
                    #pragma unroll
                    for (int nn = 0; nn < 2; nn++) {
                        int j8 = j * 2 + nn, br = nn * 2;
                        MMA_BF16(d[mi][j8], ah[mi], bh[br], bh[br + 1]);
                        MMA_BF16(d[mi][j8], al[mi], bh[br], bh[br + 1]);
                        MMA_BF16(d[mi][j8], ah[mi], bl[br], bl[br + 1]);
                    }
            }
        }
    }

    // epilogue
    #pragma unroll
    for (int mi = 0; mi < 4; mi++) {
        int row0 = x0 + warp_m + mi * 16 + (lane >> 2);
        float invd0 = 1.0f / fmaxf(g_denom[b * NN + row0],     1e-12f);
        float invd1 = 1.0f / fmaxf(g_denom[b * NN + row0 + 8], 1e-12f);
        #pragma unroll
        for (int j8 = 0; j8 < 8; j8++) {
            int col = b * 256 + warp_n + j8 * 8 + 2 * (lane & 3);
            float2 v0 = make_float2(d[mi][j8][0] * invd0, d[mi][j8][1] * invd0);
            float2 v1 = make_float2(d[mi][j8][2] * invd1, d[mi][j8][3] * invd1);
            *(float2*)&g_att[(size_t)row0 * BH + col]       = v0;
            *(float2*)&g_att[(size_t)(row0 + 8) * BH + col] = v1;
        }
    }
}

// ---------------- fc_v + elu + residual -------------------------------------
__global__ void __launch_bounds__(256) k_fc(const float* __restrict__ Wv,
                                            const float* __restrict__ bv,
                                            const float* __restrict__ h0,
                                            float* __restrict__ out)
{
    extern __shared__ float sm[];
    float (*As)[68]  = (float(*)[68])sm;
    float (*Bs)[128] = (float(*)[128])(sm + 128 * 68);

    int x0 = blockIdx.x * 128;
    int c0 = blockIdx.y * 128;
    int tid = threadIdx.x;
    int tx = tid & 15, ty = tid >> 4;

    float acc[8][8] = {};

    for (int kk = 0; kk < BH; kk += 64) {
        for (int i = tid; i < 128 * 16; i += 256) {
            int r = i >> 4, c = (i & 15) << 2;
            *(float4*)&As[r][c] = *(const float4*)&g_att[(size_t)(x0 + r) * BH + kk + c];
        }
        for (int i = tid; i < 64 * 32; i += 256) {
            int r = i >> 5, c = (i & 31) << 2;
            *(float4*)&Bs[r][c] = *(const float4*)&Wv[(size_t)(kk + r) * H + c0 + c];
        }
        __syncthreads();
        #pragma unroll 4
        for (int k = 0; k < 64; k++) {
            float av[8];
            #pragma unroll
            for (int i = 0; i < 8; i++) av[i] = As[ty * 8 + i][k];
            float4 b0 = *(const float4*)&Bs[k][tx * 4];
            float4 b1 = *(const float4*)&Bs[k][64 + tx * 4];
            #pragma unroll
            for (int i = 0; i < 8; i++) {
                acc[i][0] = fmaf(av[i], b0.x, acc[i][0]);
                acc[i][1] = fmaf(av[i], b0.y, acc[i][1]);
                acc[i][2] = fmaf(av[i], b0.z, acc[i][2]);
                acc[i][3] = fmaf(av[i], b0.w, acc[i][3]);
                acc[i][4] = fmaf(av[i], b1.x, acc[i][4]);
                acc[i][5] = fmaf(av[i], b1.y, acc[i][5]);
                acc[i][6] = fmaf(av[i], b1.z, acc[i][6]);
                acc[i][7] = fmaf(av[i], b1.w, acc[i][7]);
            }
        }
        __syncthreads();
    }

    #pragma unroll
    for (int i = 0; i < 8; i++) {
        int x = x0 + ty * 8 + i;
        #pragma unroll
        for (int half = 0; half < 2; half++) {
            float4 v;
            float* a = &acc[i][half * 4];
            int col = c0 + half * 64 + tx * 4;
            float r0 = a[0] + bv[col + 0];
            float r1 = a[1] + bv[col + 1];
            float r2 = a[2] + bv[col + 2];
            float r3 = a[3] + bv[col + 3];
            r0 = (r0 > 0.f) ? r0 : expm1f(r0);
            r1 = (r1 > 0.f) ? r1 : expm1f(r1);
            r2 = (r2 > 0.f) ? r2 : expm1f(r2);
            r3 = (r3 > 0.f) ? r3 : expm1f(r3);
            v.x = r0 + h0[(size_t)x * H + col + 0];
            v.y = r1 + h0[(size_t)x * H + col + 1];
            v.z = r2 + h0[(size_t)x * H + col + 2];
            v.w = r3 + h0[(size_t)x * H + col + 3];
            *(float4*)&out[(size_t)x * H + col] = v;
        }
    }
}

// ---------------- kl scalar output ------------------------------------------
__global__ void k_klout(float* __restrict__ out, int out_size) {
    if (threadIdx.x == 0 && out_size > NN * H) {
        out[out_size - 1] = (float)(g_kl / (double)((size_t)NN * NN));
    }
}

// ---------------- launch -----------------------------------------------------
extern "C" void kernel_launch(void* const* d_in, const int* in_sizes, int n_in,
                              void* d_out, int out_size)
{
    const float* h     = (const float*)d_in[0];
    const float* gamma = (const float*)d_in[1];
    const float* beta  = (const float*)d_in[2];
    const float* Wk    = (const float*)d_in[3];
    const float* bk    = (const float*)d_in[4];
    const float* Wm    = (const float*)d_in[5];
    const float* bm    = (const float*)d_in[6];
    const float* Wl    = (const float*)d_in[7];
    const float* bl    = (const float*)d_in[8];
    const float* Wv    = (const float*)d_in[9];
    const float* bv    = (const float*)d_in[10];
    const float* diff  = (const float*)d_in[11];
    const float* eps   = (const float*)d_in[12];
    float* out = (float*)d_out;

    const int smem_fc = (128 * 68 + 64 * 128) * 4;
    cudaFuncSetAttribute(k_scores_mma, cudaFuncAttributeMaxDynamicSharedMemorySize, SC_SMEM);
    cudaFuncSetAttribute(k_agg_mma,    cudaFuncAttributeMaxDynamicSharedMemorySize, AGG_SMEM);
    cudaFuncSetAttribute(k_fc,         cudaFuncAttributeMaxDynamicSharedMemorySize, smem_fc);

    k_init<<<48, 256>>>();
    k_ln<<<NN, 256>>>(h, gamma, beta);
    k_hnb<<<NN, 256>>>();
    k_proj<<<dim3(48, 12), 256>>>(Wk, bk, Wm, bm, Wl, bl);
    k_scores_mma<<<dim3(NB, 48, 48), 128, SC_SMEM>>>(diff, eps);
    k_agg_mma<<<dim3(24, NB), 256, AGG_SMEM>>>();
    k_fc<<<dim3(24, 2), 256, smem_fc>>>(Wv, bv, h, out);
    k_klout<<<1, 32>>>(out, out_size);
}